// round 4
// baseline (speedup 1.0000x reference)
#include <cuda_runtime.h>

// Reference semantics reduce to (softmax over a size-1 axis == 1; W is dead code):
//   out[i, 0:512]    = 2*X[i]                              for i < 64
//   out[i, 0:512]    = X[i] + sum_{r=i-64..i-1} X[r]       for i >= 64
//   out[i, 512:1024] = X[i]
//
// Two-pass: K1 builds 8-row chunk sums; K2 warms each 8-row strip's 64-row
// window from 8 chunk sums (aligned) and runs a short sliding loop.

#define NROWS  4096
#define DCOLS  512
#define LENS   64
#define CHUNK  8                 // rows per chunk (and per strip)
#define NCHUNK (NROWS / CHUNK)   // 512
#define D4     (DCOLS / 4)       // 128 float4 per row
#define OD4    (2 * D4)          // 256 float4 per output row
#define NCOPYBLK (LENS / CHUNK)  // 8 blocks for rows 0..63

// Scratch: chunk sums, 512 chunks x 128 float4 = 1 MB
__device__ float4 g_chunk[NCHUNK * D4];

__global__ __launch_bounds__(128) void chunk_sum_kernel(const float4* __restrict__ X4)
{
    const int c = threadIdx.x;       // float4 column
    const int k = blockIdx.x;        // chunk id 0..511
    const float4* p = X4 + (size_t)(k * CHUNK) * D4 + c;

    float4 s = make_float4(0.f, 0.f, 0.f, 0.f);
    #pragma unroll
    for (int j = 0; j < CHUNK; ++j) {
        float4 x = p[(size_t)j * D4];
        s.x += x.x; s.y += x.y; s.z += x.z; s.w += x.w;
    }
    g_chunk[k * D4 + c] = s;
}

__global__ __launch_bounds__(128) void slide_out_kernel(
    const float4* __restrict__ X4, float4* __restrict__ O4)
{
    const int c   = threadIdx.x;
    const int blk = blockIdx.x;

    if (blk < NCOPYBLK) {
        // rows 0..63: left = 2X, right = X
        const int i0 = blk * CHUNK;
        #pragma unroll
        for (int r = 0; r < CHUNK; ++r) {
            const int i = i0 + r;
            float4 x = X4[(size_t)i * D4 + c];
            float4 h = make_float4(2.f * x.x, 2.f * x.y, 2.f * x.z, 2.f * x.w);
            O4[(size_t)i * OD4 + c]      = h;
            O4[(size_t)i * OD4 + D4 + c] = x;
        }
        return;
    }

    // Strip s: rows [i0, i0+8), i0 = 64 + 8s. Window [i0-64, i0) = chunks s..s+7.
    const int s  = blk - NCOPYBLK;          // 0..503
    const int i0 = LENS + s * CHUNK;

    float4 w = make_float4(0.f, 0.f, 0.f, 0.f);
    #pragma unroll
    for (int j = 0; j < CHUNK; ++j) {
        float4 cs = g_chunk[(s + j) * D4 + c];
        w.x += cs.x; w.y += cs.y; w.z += cs.z; w.w += cs.w;
    }

    // Hoist all row loads (independent) before the serial update chain.
    float4 xi[CHUNK], xm[CHUNK];
    #pragma unroll
    for (int r = 0; r < CHUNK; ++r) {
        xi[r] = X4[(size_t)(i0 + r) * D4 + c];
        xm[r] = X4[(size_t)(i0 + r - LENS) * D4 + c];
    }

    #pragma unroll
    for (int r = 0; r < CHUNK; ++r) {
        const int i = i0 + r;
        float4 h = make_float4(xi[r].x + w.x, xi[r].y + w.y,
                               xi[r].z + w.z, xi[r].w + w.w);
        O4[(size_t)i * OD4 + c]      = h;
        O4[(size_t)i * OD4 + D4 + c] = xi[r];
        w.x += xi[r].x - xm[r].x;
        w.y += xi[r].y - xm[r].y;
        w.z += xi[r].z - xm[r].z;
        w.w += xi[r].w - xm[r].w;
    }
}

extern "C" void kernel_launch(void* const* d_in, const int* in_sizes, int n_in,
                              void* d_out, int out_size)
{
    const float4* X4 = (const float4*)d_in[0];   // X: (4096, 512) f32
    float4* O4 = (float4*)d_out;                 // out: (4096, 1024) f32

    chunk_sum_kernel<<<NCHUNK, 128>>>(X4);
    slide_out_kernel<<<NCOPYBLK + (NROWS - LENS) / CHUNK, 128>>>(X4, O4);
}